// round 13
// baseline (speedup 1.0000x reference)
#include <cuda_runtime.h>

#define DINL static __device__ __forceinline__

// ------------------------------ scratch (static __device__, no allocs) -----
__device__ __align__(16) float g_xs0[512 * 1024];
__device__ __align__(16) float g_xs1[512 * 1024];
__device__ __align__(16) float g_pre[512 * 4096];
__device__ __align__(16) float g_hE[2][2][512];        // [dir][parity][j]
__device__ __align__(16) float g_hdec[2][2][1024];     // [layer][parity][j]
__device__ __align__(16) float g_cdec[2048];           // [layer*1024 + j]
__device__ __align__(16) float g_logits[32000];
__device__ __align__(16) float g_prob[512u * 32000u];  // [s][v] un-normalized exp
__device__ __align__(16) short g_clfq[32000u * 1024u]; // int16 row-quantized clf_W
__device__ __align__(16) float g_clfscale[32000];      // per-row dequant scale
__device__ float g_psum[512 * 128];                    // per-step per-block partial sums
__device__ float g_sums[512];
__device__ unsigned long long g_packed[512];           // per-step argmax/max packed
// flag barrier state: groups 0-3 encoder (64 blocks), group 4 decoder (128)
__device__ unsigned g_flag[5][128];
__device__ unsigned g_relA[5 * 32];

// L2-residency split for the int16 classifier: rows < CLF_RES stay cached
// (48MB via ldcg; + 64MB fp32 LSTM weights = 112MB < 126MB L2), the rest
// (14.5MB) streams evict-first so it never evicts the resident set.
#define CLF_RES 24576

// ------------------------------ helpers ------------------------------------
// Flag-based grid barrier: no atomic contention. rank0 block is the master.
DINL void gsyncF(int grp, int rank, int nb, unsigned ctr) {
    __syncthreads();
    if (threadIdx.x == 0) {
        __threadfence();
        *(volatile unsigned*)&g_flag[grp][rank] = ctr;
    }
    if (rank == 0) {
        if ((int)threadIdx.x < nb) {
            while (*(volatile unsigned*)&g_flag[grp][threadIdx.x] < ctr) { }
        }
        __syncthreads();
        if (threadIdx.x == 0) {
            __threadfence();
            *(volatile unsigned*)&g_relA[grp * 32] = ctr;
        }
    }
    if (threadIdx.x == 0) {
        while (*(volatile unsigned*)&g_relA[grp * 32] < ctr) { }
        __threadfence();
    }
    __syncthreads();
}

DINL float wredsum(float v) {
#pragma unroll
    for (int o = 16; o > 0; o >>= 1) v += __shfl_xor_sync(0xFFFFFFFFu, v, o);
    return v;
}

DINL float sigm(float x) { return 1.0f / (1.0f + __expf(-x)); }

DINL float4 ldcg4(const float* p) { return __ldcg((const float4*)p); }
DINL float dot4(float4 a, float4 b) { return a.x * b.x + a.y * b.y + a.z * b.z + a.w * b.w; }

// ------------------------------ setup kernels ------------------------------
__global__ void zero_kernel() {
    int i = threadIdx.x;  // 1024 threads
    if (i < 512) g_packed[i] = 0ULL;
    if (i < 640) ((unsigned*)g_flag)[i] = 0u;
    if (i < 160) g_relA[i] = 0u;
}

__global__ void embed_kernel(const int* __restrict__ x, const float* __restrict__ emb) {
    int t = blockIdx.x;
    int tok = x[t];
    const float4* src = (const float4*)(emb + (size_t)tok * 1024);
    float4* dst = (float4*)(g_xs0 + (size_t)t * 1024);
    dst[threadIdx.x] = src[threadIdx.x];  // 256 threads x float4 = 1024 floats
}

// one-time per-row int16 quantization of clf_W
__global__ __launch_bounds__(256) void quant_clf_kernel(const float* __restrict__ W) {
    int v = blockIdx.x;
    int tid = threadIdx.x, lane = tid & 31, wid = tid >> 5;
    float4 w = *(const float4*)(W + (size_t)v * 1024 + tid * 4);
    float m = fmaxf(fmaxf(fabsf(w.x), fabsf(w.y)), fmaxf(fabsf(w.z), fabsf(w.w)));
#pragma unroll
    for (int o = 16; o > 0; o >>= 1) m = fmaxf(m, __shfl_xor_sync(0xFFFFFFFFu, m, o));
    __shared__ float sm[8];
    if (lane == 0) sm[wid] = m;
    __syncthreads();
    if (tid == 0) {
        float mm = sm[0];
#pragma unroll
        for (int i = 1; i < 8; i++) mm = fmaxf(mm, sm[i]);
        sm[0] = fmaxf(mm, 1e-30f);
    }
    __syncthreads();
    float mm = sm[0];
    float inv = 32767.0f / mm;
    if (tid == 0) g_clfscale[v] = mm / 32767.0f;
    short4 q;
    q.x = (short)__float2int_rn(w.x * inv);
    q.y = (short)__float2int_rn(w.y * inv);
    q.z = (short)__float2int_rn(w.z * inv);
    q.w = (short)__float2int_rn(w.w * inv);
    ((short4*)g_clfq)[(size_t)v * 256 + tid] = q;
}

// ------------------------------ encoder input GEMM -------------------------
__global__ __launch_bounds__(256) void gemm_pre_kernel(int src, const float* __restrict__ B,
                                                       const float* __restrict__ bias) {
    const float* A = src ? g_xs1 : g_xs0;
    const int K = 1024, N = 4096;
    __shared__ float As[16][128];
    __shared__ float Bs[16][128];
    int bm = blockIdx.y * 128, bn = blockIdx.x * 128;
    int tid = threadIdx.x;
    int tx = tid & 15, ty = tid >> 4;
    float acc[8][8];
#pragma unroll
    for (int i = 0; i < 8; i++)
#pragma unroll
        for (int j = 0; j < 8; j++) acc[i][j] = 0.0f;

    int lr = tid >> 2;
    int lc = (tid & 3) * 4;

    for (int kt = 0; kt < K; kt += 16) {
#pragma unroll
        for (int h = 0; h < 2; h++) {
            int r = lr + h * 64;
            float4 a4 = *(const float4*)&A[(size_t)(bm + r) * K + kt + lc];
            As[lc + 0][r] = a4.x; As[lc + 1][r] = a4.y;
            As[lc + 2][r] = a4.z; As[lc + 3][r] = a4.w;
            float4 b4 = *(const float4*)&B[(size_t)(bn + r) * K + kt + lc];
            Bs[lc + 0][r] = b4.x; Bs[lc + 1][r] = b4.y;
            Bs[lc + 2][r] = b4.z; Bs[lc + 3][r] = b4.w;
        }
        __syncthreads();
#pragma unroll
        for (int k = 0; k < 16; k++) {
            float ar[8], br[8];
            *(float4*)&ar[0] = *(const float4*)&As[k][ty * 8];
            *(float4*)&ar[4] = *(const float4*)&As[k][ty * 8 + 4];
            *(float4*)&br[0] = *(const float4*)&Bs[k][tx * 8];
            *(float4*)&br[4] = *(const float4*)&Bs[k][tx * 8 + 4];
#pragma unroll
            for (int i = 0; i < 8; i++)
#pragma unroll
                for (int j = 0; j < 8; j++) acc[i][j] += ar[i] * br[j];
        }
        __syncthreads();
    }

    float bv[8];
#pragma unroll
    for (int j = 0; j < 8; j++) bv[j] = bias[bn + tx * 8 + j];
#pragma unroll
    for (int i = 0; i < 8; i++) {
        float* Cp = g_pre + (size_t)(bm + ty * 8 + i) * N + bn + tx * 8;
#pragma unroll
        for (int j = 0; j < 8; j += 4) {
            float4 o;
            o.x = acc[i][j + 0] + bv[j + 0];
            o.y = acc[i][j + 1] + bv[j + 1];
            o.z = acc[i][j + 2] + bv[j + 2];
            o.w = acc[i][j + 3] + bv[j + 3];
            *(float4*)(Cp + j) = o;
        }
    }
}

// ------------------------------ encoder recurrence -------------------------
__global__ __launch_bounds__(256) void enc_rec_kernel(const float* __restrict__ Whh,
                                                      int layer) {
    int tid = threadIdx.x, lane = tid & 31, wid = tid >> 5;
    int grp = blockIdx.x >> 6;                    // 0=fwd 1=bwd
    int bgrp = layer * 2 + grp;                   // barrier group
    int rank = blockIdx.x & 63;
    int j = (rank << 3) + wid;                    // 0..511
    const float* W = Whh + (size_t)grp * 2048 * 512;
    float* xs_next = (layer == 0) ? g_xs1 : g_xs0;
    unsigned ctr = 1;

    float c = 0.0f;
    if (lane == 0) g_hE[grp][0][j] = 0.0f;
    gsyncF(bgrp, rank, 64, ctr++);

    const float* W0 = W + (size_t)(j) * 512;
    const float* W1 = W + (size_t)(512 + j) * 512;
    const float* W2 = W + (size_t)(1024 + j) * 512;
    const float* W3 = W + (size_t)(1536 + j) * 512;

    for (int it = 0; it < 512; it++) {
        int t = grp ? (511 - it) : it;
        int pin = it & 1, pout = pin ^ 1;
        const float* h = g_hE[grp][pin];
        float a0 = 0, a1 = 0, a2 = 0, a3 = 0;
#pragma unroll
        for (int kk = 0; kk < 4; kk++) {
            int k = kk * 128 + lane * 4;
            float4 hv = ldcg4(h + k);
            a0 += dot4(*(const float4*)(W0 + k), hv);
            a1 += dot4(*(const float4*)(W1 + k), hv);
            a2 += dot4(*(const float4*)(W2 + k), hv);
            a3 += dot4(*(const float4*)(W3 + k), hv);
        }
        a0 = wredsum(a0); a1 = wredsum(a1); a2 = wredsum(a2); a3 = wredsum(a3);
        if (lane == 0) {
            const float* pre = g_pre + (size_t)t * 4096 + grp * 2048;
            float gi = a0 + pre[j];
            float gf = a1 + pre[512 + j];
            float gg = a2 + pre[1024 + j];
            float go = a3 + pre[1536 + j];
            float iv = sigm(gi), fv = sigm(gf), gv = tanhf(gg), ov = sigm(go);
            c = fv * c + iv * gv;
            float hn = ov * tanhf(c);
            g_hE[grp][pout][j] = hn;
            xs_next[(size_t)t * 1024 + grp * 512 + j] = hn;
            if (it == 511) {
                g_hdec[layer][0][grp * 512 + j] = hn;
                g_cdec[layer * 1024 + grp * 512 + j] = c;
            }
        }
        gsyncF(bgrp, rank, 64, ctr++);
    }
}

// ------------------------------ decoder LSTM half-cell ---------------------
template <bool XCG>
DINL void lstm_part(const float* vec, const float* __restrict__ W,
                    int j, int lane, float out[4]) {
    const float* r0 = W + (size_t)(j) * 1024;
    const float* r1 = W + (size_t)(1024 + j) * 1024;
    const float* r2 = W + (size_t)(2048 + j) * 1024;
    const float* r3 = W + (size_t)(3072 + j) * 1024;
    float a0 = 0, a1 = 0, a2 = 0, a3 = 0;
#pragma unroll
    for (int kk = 0; kk < 8; kk++) {
        int k = kk * 128 + lane * 4;
        float4 xv = XCG ? ldcg4(vec + k) : *(const float4*)(vec + k);
        a0 += dot4(*(const float4*)(r0 + k), xv);
        a1 += dot4(*(const float4*)(r1 + k), xv);
        a2 += dot4(*(const float4*)(r2 + k), xv);
        a3 += dot4(*(const float4*)(r3 + k), xv);
    }
    out[0] = wredsum(a0);
    out[1] = wredsum(a1);
    out[2] = wredsum(a2);
    out[3] = wredsum(a3);
}

// int16 row helpers ----------------------------------------------------------
// Rows < CLF_RES load ldcg (L2-resident set); the tail streams evict-first.
DINL void ldrow(int4 q[4], int v, int lane) {
    const short* r = g_clfq + (size_t)v * 1024 + lane * 8;
    if (v < CLF_RES) {
#pragma unroll
        for (int c = 0; c < 4; c++) q[c] = __ldcg((const int4*)(r + c * 256));
    } else {
#pragma unroll
        for (int c = 0; c < 4; c++) q[c] = __ldcs((const int4*)(r + c * 256));
    }
}

DINL float dq2(int w, float h0, float h1) {
    int lo = (w << 16) >> 16;
    int hi = w >> 16;
    return __int2float_rn(lo) * h0 + __int2float_rn(hi) * h1;
}

DINL float dotq(const int4 q[4], const float hr[32]) {
    float a = 0.0f;
#pragma unroll
    for (int c = 0; c < 4; c++) {
        a += dq2(q[c].x, hr[c * 8 + 0], hr[c * 8 + 1]);
        a += dq2(q[c].y, hr[c * 8 + 2], hr[c * 8 + 3]);
        a += dq2(q[c].z, hr[c * 8 + 4], hr[c * 8 + 5]);
        a += dq2(q[c].w, hr[c * 8 + 6], hr[c * 8 + 7]);
    }
    return a;
}

DINL void emit(int v, float a, unsigned long long& best) {
    g_logits[v] = a;
    unsigned u = __float_as_uint(a);
    u = (u & 0x80000000u) ? ~u : (u | 0x80000000u);
    unsigned long long p = ((unsigned long long)u << 32) |
                           (unsigned long long)(0xFFFFFFFFu - (unsigned)v);
    if (p > best) best = p;
}

// ------------------------------ decoder (persistent, 128 blocks x 512 thr) -
__global__ __launch_bounds__(512, 1) void decoder_kernel(
    const float* __restrict__ dec_emb, const float* __restrict__ Wih,
    const float* __restrict__ Whh, const float* __restrict__ bias,
    const float* __restrict__ clfb) {
    const int STR = 2048;
    int tid = threadIdx.x, lane = tid & 31, wid = tid >> 5;
    int part = wid >> 3, jw = wid & 7;
    int j = blockIdx.x * 8 + jw;
    int gw = blockIdx.x * 16 + wid;  // 0..2047

    __shared__ float sgate[2][8][4];
    __shared__ unsigned long long sbest[16];
    __shared__ float sred[16];

    float c0 = g_cdec[j];
    float c1 = g_cdec[1024 + j];
    unsigned tok = 1u;  // START_IDX
    unsigned ctr = 1;

    const float* Wih1 = Wih + (size_t)4096 * 1024;
    const float* Whh1 = Whh + (size_t)4096 * 1024;
    const float* b0 = bias;
    const float* b1 = bias + 4096;

    for (int s = 0; s < 512; s++) {
        int pin = s & 1, pout = pin ^ 1;

        // ---- P1: layer 0 (16 warps: part0 = Wih*x(tok), part1 = Whh*h0) ----
        {
            float o[4];
            if (part == 0)
                lstm_part<false>(dec_emb + (size_t)tok * 1024, Wih, j, lane, o);
            else
                lstm_part<true>(g_hdec[0][pin], Whh, j, lane, o);
            if (lane == 0) {
                sgate[part][jw][0] = o[0]; sgate[part][jw][1] = o[1];
                sgate[part][jw][2] = o[2]; sgate[part][jw][3] = o[3];
            }
            __syncthreads();
            if (part == 0 && lane == 0) {
                float gi = sgate[0][jw][0] + sgate[1][jw][0] + b0[j];
                float gf = sgate[0][jw][1] + sgate[1][jw][1] + b0[1024 + j];
                float gg = sgate[0][jw][2] + sgate[1][jw][2] + b0[2048 + j];
                float go = sgate[0][jw][3] + sgate[1][jw][3] + b0[3072 + j];
                float iv = sigm(gi), fv = sigm(gf), gv = tanhf(gg), ov = sigm(go);
                c0 = fv * c0 + iv * gv;
                g_hdec[0][pout][j] = ov * tanhf(c0);
            }
        }
        gsyncF(4, blockIdx.x, 128, ctr++);

        // ---- P2: layer 1 (part0 = Wih1*h0_new, part1 = Whh1*h1_prev) ----
        {
            float o[4];
            if (part == 0)
                lstm_part<true>(g_hdec[0][pout], Wih1, j, lane, o);
            else
                lstm_part<true>(g_hdec[1][pin], Whh1, j, lane, o);
            if (lane == 0) {
                sgate[part][jw][0] = o[0]; sgate[part][jw][1] = o[1];
                sgate[part][jw][2] = o[2]; sgate[part][jw][3] = o[3];
            }
            __syncthreads();
            if (part == 0 && lane == 0) {
                float gi = sgate[0][jw][0] + sgate[1][jw][0] + b1[j];
                float gf = sgate[0][jw][1] + sgate[1][jw][1] + b1[1024 + j];
                float gg = sgate[0][jw][2] + sgate[1][jw][2] + b1[2048 + j];
                float go = sgate[0][jw][3] + sgate[1][jw][3] + b1[3072 + j];
                float iv = sigm(gi), fv = sigm(gf), gv = tanhf(gg), ov = sigm(go);
                c1 = fv * c1 + iv * gv;
                g_hdec[1][pout][j] = ov * tanhf(c1);
            }
        }
        gsyncF(4, blockIdx.x, 128, ctr++);

        // ---- P3: int16 classifier, register double-buffered 2-row batches --
        {
            float hr[32];
            const float* h1 = g_hdec[1][pout];
#pragma unroll
            for (int c = 0; c < 4; c++) {
                float4 t0 = ldcg4(h1 + c * 256 + lane * 8);
                float4 t1 = ldcg4(h1 + c * 256 + lane * 8 + 4);
                hr[c * 8 + 0] = t0.x; hr[c * 8 + 1] = t0.y;
                hr[c * 8 + 2] = t0.z; hr[c * 8 + 3] = t0.w;
                hr[c * 8 + 4] = t1.x; hr[c * 8 + 5] = t1.y;
                hr[c * 8 + 6] = t1.z; hr[c * 8 + 7] = t1.w;
            }
            unsigned long long best = 0ULL;
            int4 qA0[4], qA1[4], qB0[4], qB1[4];
            ldrow(qA0, gw, lane);
            ldrow(qA1, gw + STR, lane);
#pragma unroll 1
            for (int v = gw; v < 32000; v += 4 * STR) {
                int vb0 = v + 2 * STR, vb1 = v + 3 * STR;
                ldrow(qB0, vb0 < 32000 ? vb0 : v, lane);
                ldrow(qB1, vb1 < 32000 ? vb1 : v, lane);
                {
                    float a = wredsum(dotq(qA0, hr));
                    if (lane == 0) emit(v, a * g_clfscale[v] + clfb[v], best);
                }
                int v1 = v + STR;
                if (v1 < 32000) {
                    float a = wredsum(dotq(qA1, hr));
                    if (lane == 0) emit(v1, a * g_clfscale[v1] + clfb[v1], best);
                }
                int va0 = v + 4 * STR, va1 = v + 5 * STR;
                ldrow(qA0, va0 < 32000 ? va0 : v, lane);
                ldrow(qA1, va1 < 32000 ? va1 : v, lane);
                if (vb0 < 32000) {
                    float a = wredsum(dotq(qB0, hr));
                    if (lane == 0) emit(vb0, a * g_clfscale[vb0] + clfb[vb0], best);
                }
                if (vb1 < 32000) {
                    float a = wredsum(dotq(qB1, hr));
                    if (lane == 0) emit(vb1, a * g_clfscale[vb1] + clfb[vb1], best);
                }
            }
            if (lane == 0) sbest[wid] = best;
            __syncthreads();
            if (wid == 0) {
                unsigned long long b = (lane < 16) ? sbest[lane] : 0ULL;
#pragma unroll
                for (int o = 8; o > 0; o >>= 1) {
                    unsigned long long b2 = __shfl_xor_sync(0xFFFFFFFFu, b, o);
                    if (b2 > b) b = b2;
                }
                if (lane == 0) atomicMax(&g_packed[s], b);
            }
        }
        gsyncF(4, blockIdx.x, 128, ctr++);

        // ---- P4: exp / partial sums / next token ----
        {
            unsigned long long gp = *(volatile unsigned long long*)&g_packed[s];
            unsigned hu = (unsigned)(gp >> 32);
            float gmax = __uint_as_float((hu & 0x80000000u) ? (hu & 0x7FFFFFFFu) : ~hu);
            tok = 0xFFFFFFFFu - (unsigned)(gp & 0xFFFFFFFFu);

            float lsum = 0.0f;
            int gt = blockIdx.x * 512 + tid;
            if (gt < 32000) {
                float e = __expf(__ldcg(&g_logits[gt]) - gmax);
                __stcs(&g_prob[(size_t)s * 32000 + gt], e);
                lsum = e;
            }
            lsum = wredsum(lsum);
            if (lane == 0) sred[wid] = lsum;
            __syncthreads();
            if (tid < 32) {
                float v2 = (lane < 16) ? sred[lane] : 0.0f;
                v2 += __shfl_xor_sync(0xFFFFFFFFu, v2, 8);
                v2 += __shfl_xor_sync(0xFFFFFFFFu, v2, 4);
                v2 += __shfl_xor_sync(0xFFFFFFFFu, v2, 2);
                v2 += __shfl_xor_sync(0xFFFFFFFFu, v2, 1);
                if (lane == 0) g_psum[s * 128 + blockIdx.x] = v2;
            }
        }
    }
}

// ------------------------------ deterministic softmax sums -----------------
__global__ void sums_kernel() {
    int s = blockIdx.x;
    int lane = threadIdx.x & 31, wid = threadIdx.x >> 5;
    float v = g_psum[s * 128 + threadIdx.x];
    v = wredsum(v);
    __shared__ float sr[4];
    if (lane == 0) sr[wid] = v;
    __syncthreads();
    if (threadIdx.x == 0) g_sums[s] = (sr[0] + sr[1]) + (sr[2] + sr[3]);
}

// ------------------------------ normalize + transpose to [V,T] -------------
__global__ void norm_tr_kernel(float* __restrict__ out) {
    __shared__ float tile[32][33];
    int v0 = blockIdx.x * 32, s0 = blockIdx.y * 32;
    int tx = threadIdx.x, ty = threadIdx.y;  // 32 x 8
#pragma unroll
    for (int i = 0; i < 32; i += 8)
        tile[ty + i][tx] = g_prob[(size_t)(s0 + ty + i) * 32000 + v0 + tx];
    __syncthreads();
    float rs = 1.0f / g_sums[s0 + tx];
#pragma unroll
    for (int i = 0; i < 32; i += 8)
        out[(size_t)(v0 + ty + i) * 512 + s0 + tx] = tile[tx][ty + i] * rs;
}

// ------------------------------ launch --------------------------------------
extern "C" void kernel_launch(void* const* d_in, const int* in_sizes, int n_in,
                              void* d_out, int out_size) {
    const int*   x       = (const int*)d_in[0];
    const float* enc_emb = (const float*)d_in[1];
    const float* enc_Wih = (const float*)d_in[2];
    const float* enc_Whh = (const float*)d_in[3];
    const float* enc_b   = (const float*)d_in[4];
    const float* dec_emb = (const float*)d_in[5];
    const float* dec_Wih = (const float*)d_in[6];
    const float* dec_Whh = (const float*)d_in[7];
    const float* dec_b   = (const float*)d_in[8];
    const float* clf_W   = (const float*)d_in[9];
    const float* clf_b   = (const float*)d_in[10];
    float* out = (float*)d_out;

    zero_kernel<<<1, 1024>>>();
    embed_kernel<<<512, 256>>>(x, enc_emb);
    quant_clf_kernel<<<32000, 256>>>(clf_W);

    // encoder layer 0
    gemm_pre_kernel<<<dim3(32, 4), 256>>>(0, enc_Wih, enc_b);
    enc_rec_kernel<<<128, 256>>>(enc_Whh, 0);

    // encoder layer 1
    gemm_pre_kernel<<<dim3(32, 4), 256>>>(1, enc_Wih + (size_t)2 * 2048 * 1024,
                                          enc_b + 2 * 2048);
    enc_rec_kernel<<<128, 256>>>(enc_Whh + (size_t)2 * 2048 * 512, 1);

    // decoder (persistent, 512 greedy steps)
    decoder_kernel<<<128, 512>>>(dec_emb, dec_Wih, dec_Whh, dec_b, clf_b);

    // softmax denominators + [V,T] output
    sums_kernel<<<512, 128>>>();
    norm_tr_kernel<<<dim3(1000, 16), dim3(32, 8)>>>(out);
}

// round 14
// speedup vs baseline: 1.2617x; 1.2617x over previous
#include <cuda_runtime.h>

#define DINL static __device__ __forceinline__

// ------------------------------ scratch (static __device__, no allocs) -----
__device__ __align__(16) float g_xs0[512 * 1024];
__device__ __align__(16) float g_xs1[512 * 1024];
__device__ __align__(16) float g_pre[512 * 4096];
__device__ __align__(16) float g_hE[2][2][512];        // [dir][parity][j]
__device__ __align__(16) float g_hdec[2][2][1024];     // [layer][parity][j]
__device__ __align__(16) float g_cdec[2048];           // [layer*1024 + j]
__device__ __align__(16) float g_logits[32000];
__device__ __align__(16) float g_prob[512u * 32000u];  // [s][v] un-normalized exp
__device__ __align__(16) short g_clfq[32000u * 1024u]; // int16 row-quantized clf_W
__device__ __align__(16) float g_clfscale[32000];      // per-row dequant scale
__device__ float g_psum[512 * 128];                    // per-step per-block partial sums
__device__ float g_sums[512];
__device__ __align__(16) unsigned long long g_bb[128]; // per-block packed argmax
// flag barrier state: groups 0-3 encoder (64 blocks), group 4 decoder (128)
__device__ unsigned g_flag[5][128];
__device__ unsigned g_relA[5 * 32];

// ------------------------------ helpers ------------------------------------
// Flag-based grid barrier: no atomic contention. rank0 block is the master.
DINL void gsyncF(int grp, int rank, int nb, unsigned ctr) {
    __syncthreads();
    if (threadIdx.x == 0) {
        __threadfence();
        *(volatile unsigned*)&g_flag[grp][rank] = ctr;
    }
    if (rank == 0) {
        if ((int)threadIdx.x < nb) {
            while (*(volatile unsigned*)&g_flag[grp][threadIdx.x] < ctr) { }
        }
        __syncthreads();
        if (threadIdx.x == 0) {
            __threadfence();
            *(volatile unsigned*)&g_relA[grp * 32] = ctr;
        }
    }
    if (threadIdx.x == 0) {
        while (*(volatile unsigned*)&g_relA[grp * 32] < ctr) { }
        __threadfence();
    }
    __syncthreads();
}

DINL float wredsum(float v) {
#pragma unroll
    for (int o = 16; o > 0; o >>= 1) v += __shfl_xor_sync(0xFFFFFFFFu, v, o);
    return v;
}

DINL float sigm(float x) { return 1.0f / (1.0f + __expf(-x)); }

DINL float4 ldcg4(const float* p) { return __ldcg((const float4*)p); }
DINL float dot4(float4 a, float4 b) { return a.x * b.x + a.y * b.y + a.z * b.z + a.w * b.w; }

// ------------------------------ setup kernels ------------------------------
__global__ void zero_kernel() {
    int i = threadIdx.x;  // 1024 threads
    if (i < 640) ((unsigned*)g_flag)[i] = 0u;
    if (i < 160) g_relA[i] = 0u;
}

__global__ void embed_kernel(const int* __restrict__ x, const float* __restrict__ emb) {
    int t = blockIdx.x;
    int tok = x[t];
    const float4* src = (const float4*)(emb + (size_t)tok * 1024);
    float4* dst = (float4*)(g_xs0 + (size_t)t * 1024);
    dst[threadIdx.x] = src[threadIdx.x];  // 256 threads x float4 = 1024 floats
}

// one-time per-row int16 quantization of clf_W
__global__ __launch_bounds__(256) void quant_clf_kernel(const float* __restrict__ W) {
    int v = blockIdx.x;
    int tid = threadIdx.x, lane = tid & 31, wid = tid >> 5;
    float4 w = *(const float4*)(W + (size_t)v * 1024 + tid * 4);
    float m = fmaxf(fmaxf(fabsf(w.x), fabsf(w.y)), fmaxf(fabsf(w.z), fabsf(w.w)));
#pragma unroll
    for (int o = 16; o > 0; o >>= 1) m = fmaxf(m, __shfl_xor_sync(0xFFFFFFFFu, m, o));
    __shared__ float sm[8];
    if (lane == 0) sm[wid] = m;
    __syncthreads();
    if (tid == 0) {
        float mm = sm[0];
#pragma unroll
        for (int i = 1; i < 8; i++) mm = fmaxf(mm, sm[i]);
        sm[0] = fmaxf(mm, 1e-30f);
    }
    __syncthreads();
    float mm = sm[0];
    float inv = 32767.0f / mm;
    if (tid == 0) g_clfscale[v] = mm / 32767.0f;
    short4 q;
    q.x = (short)__float2int_rn(w.x * inv);
    q.y = (short)__float2int_rn(w.y * inv);
    q.z = (short)__float2int_rn(w.z * inv);
    q.w = (short)__float2int_rn(w.w * inv);
    ((short4*)g_clfq)[(size_t)v * 256 + tid] = q;
}

// ------------------------------ encoder input GEMM -------------------------
__global__ __launch_bounds__(256) void gemm_pre_kernel(int src, const float* __restrict__ B,
                                                       const float* __restrict__ bias) {
    const float* A = src ? g_xs1 : g_xs0;
    const int K = 1024, N = 4096;
    __shared__ float As[16][128];
    __shared__ float Bs[16][128];
    int bm = blockIdx.y * 128, bn = blockIdx.x * 128;
    int tid = threadIdx.x;
    int tx = tid & 15, ty = tid >> 4;
    float acc[8][8];
#pragma unroll
    for (int i = 0; i < 8; i++)
#pragma unroll
        for (int j = 0; j < 8; j++) acc[i][j] = 0.0f;

    int lr = tid >> 2;
    int lc = (tid & 3) * 4;

    for (int kt = 0; kt < K; kt += 16) {
#pragma unroll
        for (int h = 0; h < 2; h++) {
            int r = lr + h * 64;
            float4 a4 = *(const float4*)&A[(size_t)(bm + r) * K + kt + lc];
            As[lc + 0][r] = a4.x; As[lc + 1][r] = a4.y;
            As[lc + 2][r] = a4.z; As[lc + 3][r] = a4.w;
            float4 b4 = *(const float4*)&B[(size_t)(bn + r) * K + kt + lc];
            Bs[lc + 0][r] = b4.x; Bs[lc + 1][r] = b4.y;
            Bs[lc + 2][r] = b4.z; Bs[lc + 3][r] = b4.w;
        }
        __syncthreads();
#pragma unroll
        for (int k = 0; k < 16; k++) {
            float ar[8], br[8];
            *(float4*)&ar[0] = *(const float4*)&As[k][ty * 8];
            *(float4*)&ar[4] = *(const float4*)&As[k][ty * 8 + 4];
            *(float4*)&br[0] = *(const float4*)&Bs[k][tx * 8];
            *(float4*)&br[4] = *(const float4*)&Bs[k][tx * 8 + 4];
#pragma unroll
            for (int i = 0; i < 8; i++)
#pragma unroll
                for (int j = 0; j < 8; j++) acc[i][j] += ar[i] * br[j];
        }
        __syncthreads();
    }

    float bv[8];
#pragma unroll
    for (int j = 0; j < 8; j++) bv[j] = bias[bn + tx * 8 + j];
#pragma unroll
    for (int i = 0; i < 8; i++) {
        float* Cp = g_pre + (size_t)(bm + ty * 8 + i) * N + bn + tx * 8;
#pragma unroll
        for (int j = 0; j < 8; j += 4) {
            float4 o;
            o.x = acc[i][j + 0] + bv[j + 0];
            o.y = acc[i][j + 1] + bv[j + 1];
            o.z = acc[i][j + 2] + bv[j + 2];
            o.w = acc[i][j + 3] + bv[j + 3];
            *(float4*)(Cp + j) = o;
        }
    }
}

// ------------------------------ encoder recurrence -------------------------
__global__ __launch_bounds__(256) void enc_rec_kernel(const float* __restrict__ Whh,
                                                      int layer) {
    int tid = threadIdx.x, lane = tid & 31, wid = tid >> 5;
    int grp = blockIdx.x >> 6;                    // 0=fwd 1=bwd
    int bgrp = layer * 2 + grp;                   // barrier group
    int rank = blockIdx.x & 63;
    int j = (rank << 3) + wid;                    // 0..511
    const float* W = Whh + (size_t)grp * 2048 * 512;
    float* xs_next = (layer == 0) ? g_xs1 : g_xs0;
    unsigned ctr = 1;

    float c = 0.0f;
    if (lane == 0) g_hE[grp][0][j] = 0.0f;
    gsyncF(bgrp, rank, 64, ctr++);

    const float* W0 = W + (size_t)(j) * 512;
    const float* W1 = W + (size_t)(512 + j) * 512;
    const float* W2 = W + (size_t)(1024 + j) * 512;
    const float* W3 = W + (size_t)(1536 + j) * 512;

    for (int it = 0; it < 512; it++) {
        int t = grp ? (511 - it) : it;
        int pin = it & 1, pout = pin ^ 1;
        const float* h = g_hE[grp][pin];
        float a0 = 0, a1 = 0, a2 = 0, a3 = 0;
#pragma unroll
        for (int kk = 0; kk < 4; kk++) {
            int k = kk * 128 + lane * 4;
            float4 hv = ldcg4(h + k);
            a0 += dot4(*(const float4*)(W0 + k), hv);
            a1 += dot4(*(const float4*)(W1 + k), hv);
            a2 += dot4(*(const float4*)(W2 + k), hv);
            a3 += dot4(*(const float4*)(W3 + k), hv);
        }
        a0 = wredsum(a0); a1 = wredsum(a1); a2 = wredsum(a2); a3 = wredsum(a3);
        if (lane == 0) {
            const float* pre = g_pre + (size_t)t * 4096 + grp * 2048;
            float gi = a0 + pre[j];
            float gf = a1 + pre[512 + j];
            float gg = a2 + pre[1024 + j];
            float go = a3 + pre[1536 + j];
            float iv = sigm(gi), fv = sigm(gf), gv = tanhf(gg), ov = sigm(go);
            c = fv * c + iv * gv;
            float hn = ov * tanhf(c);
            g_hE[grp][pout][j] = hn;
            xs_next[(size_t)t * 1024 + grp * 512 + j] = hn;
            if (it == 511) {
                g_hdec[layer][0][grp * 512 + j] = hn;
                g_cdec[layer * 1024 + grp * 512 + j] = c;
            }
        }
        gsyncF(bgrp, rank, 64, ctr++);
    }
}

// ------------------------------ decoder LSTM half-cell ---------------------
template <bool XCG>
DINL void lstm_part(const float* vec, const float* __restrict__ W,
                    int j, int lane, float out[4]) {
    const float* r0 = W + (size_t)(j) * 1024;
    const float* r1 = W + (size_t)(1024 + j) * 1024;
    const float* r2 = W + (size_t)(2048 + j) * 1024;
    const float* r3 = W + (size_t)(3072 + j) * 1024;
    float a0 = 0, a1 = 0, a2 = 0, a3 = 0;
#pragma unroll
    for (int kk = 0; kk < 8; kk++) {
        int k = kk * 128 + lane * 4;
        float4 xv = XCG ? ldcg4(vec + k) : *(const float4*)(vec + k);
        a0 += dot4(*(const float4*)(r0 + k), xv);
        a1 += dot4(*(const float4*)(r1 + k), xv);
        a2 += dot4(*(const float4*)(r2 + k), xv);
        a3 += dot4(*(const float4*)(r3 + k), xv);
    }
    out[0] = wredsum(a0);
    out[1] = wredsum(a1);
    out[2] = wredsum(a2);
    out[3] = wredsum(a3);
}

// int16 row helpers ----------------------------------------------------------
DINL void ldrow(int4 q[4], int v, int lane) {
    const short* r = g_clfq + (size_t)v * 1024 + lane * 8;
#pragma unroll
    for (int c = 0; c < 4; c++) q[c] = __ldcs((const int4*)(r + c * 256));
}

DINL float dq2(int w, float h0, float h1) {
    int lo = (w << 16) >> 16;
    int hi = w >> 16;
    return __int2float_rn(lo) * h0 + __int2float_rn(hi) * h1;
}

DINL float dotq(const int4 q[4], const float hr[32]) {
    float a = 0.0f;
#pragma unroll
    for (int c = 0; c < 4; c++) {
        a += dq2(q[c].x, hr[c * 8 + 0], hr[c * 8 + 1]);
        a += dq2(q[c].y, hr[c * 8 + 2], hr[c * 8 + 3]);
        a += dq2(q[c].z, hr[c * 8 + 4], hr[c * 8 + 5]);
        a += dq2(q[c].w, hr[c * 8 + 6], hr[c * 8 + 7]);
    }
    return a;
}

DINL void emit(int v, float a, unsigned long long& best) {
    g_logits[v] = a;
    unsigned u = __float_as_uint(a);
    u = (u & 0x80000000u) ? ~u : (u | 0x80000000u);
    unsigned long long p = ((unsigned long long)u << 32) |
                           (unsigned long long)(0xFFFFFFFFu - (unsigned)v);
    if (p > best) best = p;
}

// ------------------------------ decoder (persistent, 128 blocks x 512 thr) -
__global__ __launch_bounds__(512, 1) void decoder_kernel(
    const float* __restrict__ dec_emb, const float* __restrict__ Wih,
    const float* __restrict__ Whh, const float* __restrict__ bias,
    const float* __restrict__ clfb) {
    const int STR = 2048;
    int tid = threadIdx.x, lane = tid & 31, wid = tid >> 5;
    int part = wid >> 3, jw = wid & 7;
    int j = blockIdx.x * 8 + jw;
    int gw = blockIdx.x * 16 + wid;  // 0..2047

    __shared__ float sgate[2][8][4];
    __shared__ unsigned long long sbest[16];
    __shared__ unsigned long long gp_s;
    __shared__ float sred[16];

    float c0 = g_cdec[j];
    float c1 = g_cdec[1024 + j];
    unsigned tok = 1u;  // START_IDX
    unsigned ctr = 1;

    const float* Wih1 = Wih + (size_t)4096 * 1024;
    const float* Whh1 = Whh + (size_t)4096 * 1024;
    const float* b0 = bias;
    const float* b1 = bias + 4096;

    for (int s = 0; s < 512; s++) {
        int pin = s & 1, pout = pin ^ 1;

        // ---- P1: layer 0 (16 warps: part0 = Wih*x(tok), part1 = Whh*h0) ----
        {
            float o[4];
            if (part == 0)
                lstm_part<false>(dec_emb + (size_t)tok * 1024, Wih, j, lane, o);
            else
                lstm_part<true>(g_hdec[0][pin], Whh, j, lane, o);
            if (lane == 0) {
                sgate[part][jw][0] = o[0]; sgate[part][jw][1] = o[1];
                sgate[part][jw][2] = o[2]; sgate[part][jw][3] = o[3];
            }
            __syncthreads();
            if (part == 0 && lane == 0) {
                float gi = sgate[0][jw][0] + sgate[1][jw][0] + b0[j];
                float gf = sgate[0][jw][1] + sgate[1][jw][1] + b0[1024 + j];
                float gg = sgate[0][jw][2] + sgate[1][jw][2] + b0[2048 + j];
                float go = sgate[0][jw][3] + sgate[1][jw][3] + b0[3072 + j];
                float iv = sigm(gi), fv = sigm(gf), gv = tanhf(gg), ov = sigm(go);
                c0 = fv * c0 + iv * gv;
                g_hdec[0][pout][j] = ov * tanhf(c0);
            }
        }
        gsyncF(4, blockIdx.x, 128, ctr++);

        // ---- P2: layer 1 (part0 = Wih1*h0_new, part1 = Whh1*h1_prev) ----
        {
            float o[4];
            if (part == 0)
                lstm_part<true>(g_hdec[0][pout], Wih1, j, lane, o);
            else
                lstm_part<true>(g_hdec[1][pin], Whh1, j, lane, o);
            if (lane == 0) {
                sgate[part][jw][0] = o[0]; sgate[part][jw][1] = o[1];
                sgate[part][jw][2] = o[2]; sgate[part][jw][3] = o[3];
            }
            __syncthreads();
            if (part == 0 && lane == 0) {
                float gi = sgate[0][jw][0] + sgate[1][jw][0] + b1[j];
                float gf = sgate[0][jw][1] + sgate[1][jw][1] + b1[1024 + j];
                float gg = sgate[0][jw][2] + sgate[1][jw][2] + b1[2048 + j];
                float go = sgate[0][jw][3] + sgate[1][jw][3] + b1[3072 + j];
                float iv = sigm(gi), fv = sigm(gf), gv = tanhf(gg), ov = sigm(go);
                c1 = fv * c1 + iv * gv;
                g_hdec[1][pout][j] = ov * tanhf(c1);
            }
        }
        gsyncF(4, blockIdx.x, 128, ctr++);

        // ---- P3: int16 classifier, register double-buffered 2-row batches --
        {
            float hr[32];
            const float* h1 = g_hdec[1][pout];
#pragma unroll
            for (int c = 0; c < 4; c++) {
                float4 t0 = ldcg4(h1 + c * 256 + lane * 8);
                float4 t1 = ldcg4(h1 + c * 256 + lane * 8 + 4);
                hr[c * 8 + 0] = t0.x; hr[c * 8 + 1] = t0.y;
                hr[c * 8 + 2] = t0.z; hr[c * 8 + 3] = t0.w;
                hr[c * 8 + 4] = t1.x; hr[c * 8 + 5] = t1.y;
                hr[c * 8 + 6] = t1.z; hr[c * 8 + 7] = t1.w;
            }
            unsigned long long best = 0ULL;
            int4 qA0[4], qA1[4], qB0[4], qB1[4];
            ldrow(qA0, gw, lane);
            ldrow(qA1, gw + STR, lane);
#pragma unroll 1
            for (int v = gw; v < 32000; v += 4 * STR) {
                int vb0 = v + 2 * STR, vb1 = v + 3 * STR;
                ldrow(qB0, vb0 < 32000 ? vb0 : v, lane);
                ldrow(qB1, vb1 < 32000 ? vb1 : v, lane);
                {
                    float a = wredsum(dotq(qA0, hr));
                    if (lane == 0) emit(v, a * g_clfscale[v] + clfb[v], best);
                }
                int v1 = v + STR;
                if (v1 < 32000) {
                    float a = wredsum(dotq(qA1, hr));
                    if (lane == 0) emit(v1, a * g_clfscale[v1] + clfb[v1], best);
                }
                int va0 = v + 4 * STR, va1 = v + 5 * STR;
                ldrow(qA0, va0 < 32000 ? va0 : v, lane);
                ldrow(qA1, va1 < 32000 ? va1 : v, lane);
                if (vb0 < 32000) {
                    float a = wredsum(dotq(qB0, hr));
                    if (lane == 0) emit(vb0, a * g_clfscale[vb0] + clfb[vb0], best);
                }
                if (vb1 < 32000) {
                    float a = wredsum(dotq(qB1, hr));
                    if (lane == 0) emit(vb1, a * g_clfscale[vb1] + clfb[vb1], best);
                }
            }
            if (lane == 0) sbest[wid] = best;
            __syncthreads();
            if (wid == 0) {
                unsigned long long b = (lane < 16) ? sbest[lane] : 0ULL;
#pragma unroll
                for (int o = 8; o > 0; o >>= 1) {
                    unsigned long long b2 = __shfl_xor_sync(0xFFFFFFFFu, b, o);
                    if (b2 > b) b = b2;
                }
                if (lane == 0) g_bb[blockIdx.x] = b;  // visibility via gsyncF
            }
        }
        gsyncF(4, blockIdx.x, 128, ctr++);

        // ---- P4: global argmax from g_bb, then exp / partial sums ----
        {
            if (wid == 0) {
                unsigned long long b = __ldcg(&g_bb[lane]);
                unsigned long long b2 = __ldcg(&g_bb[lane + 32]);
                if (b2 > b) b = b2;
                b2 = __ldcg(&g_bb[lane + 64]);
                if (b2 > b) b = b2;
                b2 = __ldcg(&g_bb[lane + 96]);
                if (b2 > b) b = b2;
#pragma unroll
                for (int o = 16; o > 0; o >>= 1) {
                    unsigned long long t2 = __shfl_xor_sync(0xFFFFFFFFu, b, o);
                    if (t2 > b) b = t2;
                }
                if (lane == 0) gp_s = b;
            }
            __syncthreads();
            unsigned long long gp = gp_s;
            unsigned hu = (unsigned)(gp >> 32);
            float gmax = __uint_as_float((hu & 0x80000000u) ? (hu & 0x7FFFFFFFu) : ~hu);
            tok = 0xFFFFFFFFu - (unsigned)(gp & 0xFFFFFFFFu);

            float lsum = 0.0f;
            int gt = blockIdx.x * 512 + tid;
            if (gt < 32000) {
                float e = __expf(__ldcg(&g_logits[gt]) - gmax);
                __stcs(&g_prob[(size_t)s * 32000 + gt], e);
                lsum = e;
            }
            lsum = wredsum(lsum);
            if (lane == 0) sred[wid] = lsum;
            __syncthreads();
            if (tid < 32) {
                float v2 = (lane < 16) ? sred[lane] : 0.0f;
                v2 += __shfl_xor_sync(0xFFFFFFFFu, v2, 8);
                v2 += __shfl_xor_sync(0xFFFFFFFFu, v2, 4);
                v2 += __shfl_xor_sync(0xFFFFFFFFu, v2, 2);
                v2 += __shfl_xor_sync(0xFFFFFFFFu, v2, 1);
                if (lane == 0) g_psum[s * 128 + blockIdx.x] = v2;
            }
        }
    }
}

// ------------------------------ deterministic softmax sums -----------------
__global__ void sums_kernel() {
    int s = blockIdx.x;
    int lane = threadIdx.x & 31, wid = threadIdx.x >> 5;
    float v = g_psum[s * 128 + threadIdx.x];
    v = wredsum(v);
    __shared__ float sr[4];
    if (lane == 0) sr[wid] = v;
    __syncthreads();
    if (threadIdx.x == 0) g_sums[s] = (sr[0] + sr[1]) + (sr[2] + sr[3]);
}

// ------------------------------ normalize + transpose to [V,T] -------------
__global__ void norm_tr_kernel(float* __restrict__ out) {
    __shared__ float tile[32][33];
    int v0 = blockIdx.x * 32, s0 = blockIdx.y * 32;
    int tx = threadIdx.x, ty = threadIdx.y;  // 32 x 8
#pragma unroll
    for (int i = 0; i < 32; i += 8)
        tile[ty + i][tx] = g_prob[(size_t)(s0 + ty + i) * 32000 + v0 + tx];
    __syncthreads();
    float rs = 1.0f / g_sums[s0 + tx];
#pragma unroll
    for (int i = 0; i < 32; i += 8)
        out[(size_t)(v0 + ty + i) * 512 + s0 + tx] = tile[tx][ty + i] * rs;
}

// ------------------------------ launch --------------------------------------
extern "C" void kernel_launch(void* const* d_in, const int* in_sizes, int n_in,
                              void* d_out, int out_size) {
    const int*   x       = (const int*)d_in[0];
    const float* enc_emb = (const float*)d_in[1];
    const float* enc_Wih = (const float*)d_in[2];
    const float* enc_Whh = (const float*)d_in[3];
    const float* enc_b   = (const float*)d_in[4];
    const float* dec_emb = (const float*)d_in[5];
    const float* dec_Wih = (const float*)d_in[6];
    const float* dec_Whh = (const float*)d_in[7];
    const float* dec_b   = (const float*)d_in[8];
    const float* clf_W   = (const float*)d_in[9];
    const float* clf_b   = (const float*)d_in[10];
    float* out = (float*)d_out;

    zero_kernel<<<1, 1024>>>();
    embed_kernel<<<512, 256>>>(x, enc_emb);
    quant_clf_kernel<<<32000, 256>>>(clf_W);

    // encoder layer 0
    gemm_pre_kernel<<<dim3(32, 4), 256>>>(0, enc_Wih, enc_b);
    enc_rec_kernel<<<128, 256>>>(enc_Whh, 0);

    // encoder layer 1
    gemm_pre_kernel<<<dim3(32, 4), 256>>>(1, enc_Wih + (size_t)2 * 2048 * 1024,
                                          enc_b + 2 * 2048);
    enc_rec_kernel<<<128, 256>>>(enc_Whh + (size_t)2 * 2048 * 512, 1);

    // decoder (persistent, 512 greedy steps)
    decoder_kernel<<<128, 512>>>(dec_emb, dec_Wih, dec_Whh, dec_b, clf_b);

    // softmax denominators + [V,T] output
    sums_kernel<<<512, 128>>>();
    norm_tr_kernel<<<dim3(1000, 16), dim3(32, 8)>>>(out);
}